// round 8
// baseline (speedup 1.0000x reference)
#include <cuda_runtime.h>
#include <cuda_fp16.h>
#include <cstdint>

#define Bx 256
#define Kc 16
#define Nn 1024
#define F144 144
#define HID 128
#define NC 16

#define PITCH 304            // bytes per row of ctx / w1t tiles (152 halves)
#define PITCH_H 152
#define HP 136               // halves per row of h / w2t tiles (272 bytes)

// ---------------- device scratch (allocation-free rule) ----------------
__device__ __align__(16) unsigned short g_z2[64 * 64 * 256 * 16];     // 32 MB: [h][w][b][k] fp16
__device__ __align__(16) unsigned short g_w1t[16 * HID * PITCH_H];    // 1.2 MB: per-bs W1eff^T fp16 [hid][f]
__device__ int g_cnt;

// ---------------- helpers ----------------
__device__ __forceinline__ uint32_t smem_u32(const void* p) {
    uint32_t a;
    asm("{ .reg .u64 t; cvta.to.shared.u64 t, %1; cvt.u32.u64 %0, t; }" : "=r"(a) : "l"(p));
    return a;
}
__device__ __forceinline__ void ldsm4(uint32_t* r, uint32_t addr) {
    asm volatile("ldmatrix.sync.aligned.m8n8.x4.shared.b16 {%0,%1,%2,%3}, [%4];"
        : "=r"(r[0]), "=r"(r[1]), "=r"(r[2]), "=r"(r[3]) : "r"(addr));
}
__device__ __forceinline__ void hmma(float* c, const uint32_t* a, uint32_t b0, uint32_t b1) {
    asm volatile("mma.sync.aligned.m16n8k16.row.col.f32.f16.f16.f32 "
        "{%0,%1,%2,%3},{%4,%5,%6,%7},{%8,%9},{%0,%1,%2,%3};"
        : "+f"(c[0]), "+f"(c[1]), "+f"(c[2]), "+f"(c[3])
        : "r"(a[0]), "r"(a[1]), "r"(a[2]), "r"(a[3]), "r"(b0), "r"(b1));
}
#define CP16(dst, src) asm volatile("cp.async.cg.shared.global [%0], [%1], 16;" :: "r"(dst), "l"(src))
#define CP_COMMIT()    asm volatile("cp.async.commit_group;" ::: "memory")
#define CP_WAIT(n)     asm volatile("cp.async.wait_group %0;" :: "n"(n) : "memory")

// ---------------- repack z (B,K,H,W) int32 -> [h][w][b][k] fp16 ----------------
__global__ void repack2_k(const int* __restrict__ z) {
    int b = blockIdx.x >> 6, h = blockIdx.x & 63;
    __shared__ unsigned short s[1024];  // [k][w]
    for (int idx = threadIdx.x; idx < 1024; idx += 256) {
        int k = idx >> 6, w = idx & 63;
        s[k * 64 + w] = __half_as_ushort(__float2half((float)z[((b * Kc + k) * 64 + h) * 64 + w]));
    }
    __syncthreads();
    unsigned int* out = (unsigned int*)g_z2;
    for (int idx = threadIdx.x; idx < 512; idx += 256) {
        int w = idx >> 3, k2 = idx & 7;
        unsigned int v = (unsigned int)s[(2 * k2) * 64 + w]
                       | ((unsigned int)s[(2 * k2 + 1) * 64 + w] << 16);
        out[((h * 64 + w) * 256 + b) * 8 + k2] = v;
    }
}

// ---------------- build W1T tiles: g_w1t[s][hid][f] = W1eff(f,hid)/15, fp16 ----------------
__global__ void weff3_k(const float* __restrict__ W1) {
    if (blockIdx.x == 0 && blockIdx.y == 0 && threadIdx.x == 0) g_cnt = 0;
    int s = blockIdx.y;
    int elem = blockIdx.x * 512 + threadIdx.x;   // 0 .. 128*152-1
    int h = elem / PITCH_H, f = elem % PITCH_H;
    int drop = 64 + s;
    float w = 0.0f;
    if (f < F144) w = (f < drop) ? W1[f * HID + h] : (f > drop ? W1[(f - 1) * HID + h] : 0.0f);
    g_w1t[(s * HID + h) * PITCH_H + f] = __half_as_ushort(__float2half(w * (1.0f / 15.0f)));
}

__global__ void fin_k(float* out) { out[0] = (float)g_cnt * (1.0f / (float)(Nn * Bx)); }

// ---------------- main: one block per 2 n's, cp.async double-buffered ctx ----------------
// dyn smem layout:
//   ctxA fp16 [256][PITCH] @0        77824   (phase2 of n0: hs_A overlays, 69632)
//   ctxB fp16 [256][PITCH] @77824    77824   (phase2 of n1: hs_B overlays)
//   w1t  fp16 [128][PITCH] @155648   38912   (restaged between n0 and n1)
//   w2t  fp16 [16][HP]     @194560   4352
//   b1   f32               @198912   512
//   b2   f32               @199424   64
#define SM_CTXA 0
#define SM_CTXB 77824
#define SM_W1T  155648
#define SM_W2T  194560
#define SM_B1   198912
#define SM_B2   199424
#define SM_TOT  199488

struct NP { int bs, ii, jj; };

__device__ __forceinline__ void fill_ctx_async(uint32_t smb, uint32_t ctx_off, NP p, int t) {
    for (int idx = t; idx < 9 * 256; idx += 512) {
        int b = idx & 255, m = idx >> 8;
        int ni = (p.ii + (m / 3) - 1) & 63;
        int nj = (p.jj + (m % 3) - 1) & 63;
        const char* src = (const char*)&g_z2[(((ni * 64) + nj) * 256 + b) * 16];
        uint32_t dst = smb + ctx_off + (uint32_t)b * PITCH + (uint32_t)m * 32;
        CP16(dst, src);
        CP16(dst + 16, src + 16);
    }
    CP_COMMIT();
}

__device__ __forceinline__ void stage_w1t(char* smem, int bsn, int t) {
    const uint4* src = (const uint4*)(g_w1t + bsn * HID * PITCH_H);
    uint4* dst = (uint4*)(smem + SM_W1T);
    #pragma unroll
    for (int i = 0; i < (HID * PITCH / 16) / 512; i++) dst[t + i * 512] = src[t + i * 512];
    // HID*PITCH/16 = 2432, not multiple of 512: handle remainder
    int rem = t + ((HID * PITCH / 16) / 512) * 512;
    if (rem < HID * PITCH / 16) dst[rem] = src[rem];
}

// computes GEMM1 + epilogue + GEMM2 + count for one n; ctx at ctx_off (hs overlays it)
__device__ __forceinline__ void compute_n(char* smem, uint32_t smb, uint32_t ctx_off,
                                          NP p, int t, int* cnt) {
    int w = t >> 5, lane = t & 31;
    float* b1s = (float*)(smem + SM_B1);
    float* b2s = (float*)(smem + SM_B2);
    unsigned short* hs16 = (unsigned short*)(smem + ctx_off);

    // ---- GEMM1 (HMMA): 16 warps, 4x4 grid; warp tile 64 b x 32 hid; 9 K-steps ----
    int wm = w >> 2, wn = w & 3;
    int b0w = wm * 64, n0w = wn * 32;
    float acc[4][4][4];
    #pragma unroll
    for (int mt = 0; mt < 4; mt++)
        #pragma unroll
        for (int nt = 0; nt < 4; nt++)
            #pragma unroll
            for (int e = 0; e < 4; e++) acc[mt][nt][e] = 0.0f;
    {
        uint32_t a_base = smb + ctx_off + (uint32_t)(b0w + (lane & 15)) * PITCH + ((lane >> 4) << 4);
        uint32_t b_base = smb + SM_W1T + (uint32_t)(n0w + (lane & 7) + ((lane >> 4) << 3)) * PITCH
                          + (((lane >> 3) & 1) << 4);
        #pragma unroll
        for (int k = 0; k < 9; k++) {
            uint32_t koff = (uint32_t)k * 32;
            uint32_t af[4][4], bf[2][4];
            #pragma unroll
            for (int mt = 0; mt < 4; mt++) ldsm4(af[mt], a_base + (uint32_t)mt * (16 * PITCH) + koff);
            #pragma unroll
            for (int q = 0; q < 2; q++)   ldsm4(bf[q], b_base + (uint32_t)q * (16 * PITCH) + koff);
            #pragma unroll
            for (int mt = 0; mt < 4; mt++)
                #pragma unroll
                for (int nt = 0; nt < 4; nt++)
                    hmma(acc[mt][nt], af[mt], bf[nt >> 1][(nt & 1) * 2], bf[nt >> 1][(nt & 1) * 2 + 1]);
        }
    }
    __syncthreads();   // done reading ctx; hs16 overlays it

    // ---- epilogue: relu(acc + b1) -> hs16[b][hid] fp16 ----
    {
        int r = lane >> 2, cp = (lane & 3) * 2;
        #pragma unroll
        for (int nt = 0; nt < 4; nt++) {
            int hid = n0w + nt * 8 + cp;
            float bx = b1s[hid], by = b1s[hid + 1];
            #pragma unroll
            for (int mt = 0; mt < 4; mt++) {
                int b = b0w + mt * 16 + r;
                float v0 = acc[mt][nt][0] + bx, v1 = acc[mt][nt][1] + by;
                float v2 = acc[mt][nt][2] + bx, v3 = acc[mt][nt][3] + by;
                *(__half2*)&hs16[b * HP + hid] =
                    __floats2half2_rn(v0 > 0.f ? v0 : 0.f, v1 > 0.f ? v1 : 0.f);
                *(__half2*)&hs16[(b + 8) * HP + hid] =
                    __floats2half2_rn(v2 > 0.f ? v2 : 0.f, v3 > 0.f ? v3 : 0.f);
            }
        }
    }
    __syncthreads();

    // ---- GEMM2 (HMMA) + argmax + count: warp w handles b rows [w*16, w*16+16) ----
    {
        int b0 = w * 16;
        uint32_t a_base = smb + ctx_off + (uint32_t)(b0 + (lane & 15)) * (HP * 2) + ((lane >> 4) << 4);
        uint32_t b_base = smb + SM_W2T + (uint32_t)((lane & 7) + ((lane >> 4) << 3)) * (HP * 2)
                          + (((lane >> 3) & 1) << 4);
        float a0[4] = {0.f, 0.f, 0.f, 0.f}, a1[4] = {0.f, 0.f, 0.f, 0.f};
        #pragma unroll
        for (int k = 0; k < 8; k++) {
            uint32_t af[4], bf[4];
            ldsm4(af, a_base + (uint32_t)k * 32);
            ldsm4(bf, b_base + (uint32_t)k * 32);
            hmma(a0, af, bf[0], bf[1]);   // classes 0..7
            hmma(a1, af, bf[2], bf[3]);   // classes 8..15
        }
        int r = lane >> 2, cp = (lane & 3) * 2;
        float bz0 = b2s[cp], bz1 = b2s[cp + 1], bz8 = b2s[8 + cp], bz9 = b2s[9 + cp];

        float mx0 = a0[0] + bz0; int mi0 = cp;
        { float v = a0[1] + bz1; if (v > mx0) { mx0 = v; mi0 = cp + 1; } }
        { float v = a1[0] + bz8; if (v > mx0) { mx0 = v; mi0 = 8 + cp; } }
        { float v = a1[1] + bz9; if (v > mx0) { mx0 = v; mi0 = 9 + cp; } }
        float mx1 = a0[2] + bz0; int mi1 = cp;
        { float v = a0[3] + bz1; if (v > mx1) { mx1 = v; mi1 = cp + 1; } }
        { float v = a1[2] + bz8; if (v > mx1) { mx1 = v; mi1 = 8 + cp; } }
        { float v = a1[3] + bz9; if (v > mx1) { mx1 = v; mi1 = 9 + cp; } }

        #pragma unroll
        for (int s = 1; s <= 2; s <<= 1) {
            float o0 = __shfl_xor_sync(0xffffffffu, mx0, s);
            int   i0 = __shfl_xor_sync(0xffffffffu, mi0, s);
            if (o0 > mx0 || (o0 == mx0 && i0 < mi0)) { mx0 = o0; mi0 = i0; }
            float o1 = __shfl_xor_sync(0xffffffffu, mx1, s);
            int   i1 = __shfl_xor_sync(0xffffffffu, mi1, s);
            if (o1 > mx1 || (o1 == mx1 && i1 < mi1)) { mx1 = o1; mi1 = i1; }
        }

        if ((lane & 3) == 0) {
            int bb = b0 + r;
            size_t tbase = ((size_t)(p.ii * 64 + p.jj) * 256) * 16 + p.bs;
            int t0 = (int)__half2float(__ushort_as_half(g_z2[tbase + (size_t)bb * 16]));
            int t1 = (int)__half2float(__ushort_as_half(g_z2[tbase + (size_t)(bb + 8) * 16]));
            int e = (mi0 != t0) + (mi1 != t1);
            if (e) atomicAdd(cnt, e);
        }
    }
}

__global__ __launch_bounds__(512, 1) void main_k(
    const int* __restrict__ bs, const int* __restrict__ ii, const int* __restrict__ jj,
    const float* __restrict__ b1, const float* __restrict__ W2, const float* __restrict__ b2)
{
    extern __shared__ char smem[];
    uint32_t smb = smem_u32(smem);
    unsigned short* w2t = (unsigned short*)(smem + SM_W2T);
    float* b1s = (float*)(smem + SM_B1);
    float* b2s = (float*)(smem + SM_B2);
    __shared__ int cnt;

    int n0 = blockIdx.x, n1 = blockIdx.x + 512;
    int t = threadIdx.x;
    if (t == 0) cnt = 0;

    NP p0 = {bs[n0], ii[n0], jj[n0]};
    NP p1 = {bs[n1], ii[n1], jj[n1]};

    // ---- issue both ctx gathers up front (async), then stage weights ----
    fill_ctx_async(smb, SM_CTXA, p0, t);   // group 0 (older)
    fill_ctx_async(smb, SM_CTXB, p1, t);   // group 1
    stage_w1t(smem, p0.bs, t);
    for (int i = t; i < NC * HID; i += 512) {
        int c = i & 15, j = i >> 4;
        w2t[c * HP + j] = __half_as_ushort(__float2half(W2[j * NC + c]));
    }
    if (t < HID) b1s[t] = b1[t];
    if (t < NC)  b2s[t] = b2[t];

    CP_WAIT(1);          // ctxA complete (ctxB may still be in flight)
    __syncthreads();

    // ---- n0 ----
    compute_n(smem, smb, SM_CTXA, p0, t, &cnt);
    __syncthreads();     // all warps done with w1t before restage

    stage_w1t(smem, p1.bs, t);
    CP_WAIT(0);          // ctxB complete
    __syncthreads();

    // ---- n1 ----
    compute_n(smem, smb, SM_CTXB, p1, t, &cnt);

    __syncthreads();
    if (t == 0) atomicAdd(&g_cnt, cnt);
}

// ---------------- launch ----------------
extern "C" void kernel_launch(void* const* d_in, const int* in_sizes, int n_in,
                              void* d_out, int out_size)
{
    const int*   z  = (const int*)d_in[0];
    const int*   bs = (const int*)d_in[1];
    const int*   ii = (const int*)d_in[2];
    const int*   jj = (const int*)d_in[3];
    const float* W1 = (const float*)d_in[4];
    const float* b1 = (const float*)d_in[5];
    const float* W2 = (const float*)d_in[6];
    const float* b2 = (const float*)d_in[7];
    float* out = (float*)d_out;

    cudaFuncSetAttribute(main_k, cudaFuncAttributeMaxDynamicSharedMemorySize, SM_TOT);

    repack2_k<<<256 * 64, 256>>>(z);
    weff3_k<<<dim3((HID * PITCH_H) / 512, 16), 512>>>(W1);
    main_k<<<Nn / 2, 512, SM_TOT>>>(bs, ii, jj, b1, W2, b2);
    fin_k<<<1, 1>>>(out);
}